// round 15
// baseline (speedup 1.0000x reference)
#include <cuda_runtime.h>
#include <cstdint>

// B=8, C=16, H=512, W=512, M=N=15
//   K:     [128, 16, 16]  f32
//   basis: [262144, 16, 16] f32, separable: basis[h*W+w,p,q] = Bu[h,p]*Bv[w,q]
//   out:   [128, 512, 512] f32
//
// Bu[h,p] = sum_q basis[h*W, p, q]; Bv[w,q] = sum_p basis[w, p, q]
// T[bc,p,w] = sum_q K[bc,p,q]*Bv[w,q];  out[bc,h,w] = sum_p Bu[h,p]*T[bc,p,w]

#define HH 512
#define WW 512
#define PP 16
#define QQ 16
#define BC 128
#define ROWS 64

__device__ float g_But[PP * HH];      // Bu transposed: [p][h], 32 KB
__device__ float g_BvT[QQ * WW];      // Bv transposed: [q][w], 32 KB
__device__ float g_T[BC * PP * WW];   // T: [bc][p][w], 4 MB (L2-resident)

__device__ __forceinline__ unsigned long long pk(float a, float b) {
    unsigned long long r;
    asm("mov.b64 %0, {%1, %2};" : "=l"(r) : "f"(a), "f"(b));
    return r;
}
__device__ __forceinline__ void fma2(unsigned long long& d, unsigned long long a,
                                     unsigned long long b) {
    asm("fma.rn.f32x2 %0, %1, %2, %0;" : "+l"(d) : "l"(a), "l"(b));
}
__device__ __forceinline__ void unpk(unsigned long long v, float& a, float& b) {
    asm("mov.b64 {%0, %1}, %2;" : "=f"(a), "=f"(b) : "l"(v));
}

// ---------------------------------------------------------------------------
// Kernel A: extraction, MLP-boosted. 32 blocks x 256 threads.
//   blocks 0..15 : Bu. Block b covers h in [32b, 32b+32); warp handles 4 rows,
//                  issuing ALL 8 LDG.128 before reducing (MLP=8).
//   blocks 16..31: Bv, same structure over w.
// ---------------------------------------------------------------------------
__global__ __launch_bounds__(256) void extract_factors(const float* __restrict__ basis) {
    int warp = threadIdx.x >> 5, lane = threadIdx.x & 31;

    if (blockIdx.x < 16) {
        int hbase = blockIdx.x * 32 + warp * 4;    // 4 rows per warp
        // Issue all 8 loads up-front (rows are 512KB apart -> hide TLB/DRAM)
        float4 a[4], b[4];
        #pragma unroll
        for (int r = 0; r < 4; ++r) {
            const float4* r4 = reinterpret_cast<const float4*>(
                basis + (size_t)(hbase + r) * WW * (PP * QQ));
            a[r] = r4[lane * 2];
            b[r] = r4[lane * 2 + 1];
        }
        #pragma unroll
        for (int r = 0; r < 4; ++r) {
            float s = (a[r].x + a[r].y) + (a[r].z + a[r].w)
                    + (b[r].x + b[r].y) + (b[r].z + b[r].w);
            s += __shfl_xor_sync(0xffffffffu, s, 1);   // lanes (2k,2k+1) cover p=k
            if ((lane & 1) == 0) g_But[(lane >> 1) * HH + (hbase + r)] = s;
        }
    } else {
        int wbase = (blockIdx.x - 16) * 32 + warp * 4;
        float4 a[4], b[4];
        #pragma unroll
        for (int r = 0; r < 4; ++r) {
            const float4* r4 = reinterpret_cast<const float4*>(
                basis + (size_t)(wbase + r) * (PP * QQ));
            a[r] = r4[lane * 2];
            b[r] = r4[lane * 2 + 1];
        }
        #pragma unroll
        for (int r = 0; r < 4; ++r) {
            // lane l: p = l>>1, q = (l&1)*8 + j; butterfly over p (offsets 2..16)
            #pragma unroll
            for (int off = 2; off <= 16; off <<= 1) {
                a[r].x += __shfl_xor_sync(0xffffffffu, a[r].x, off);
                a[r].y += __shfl_xor_sync(0xffffffffu, a[r].y, off);
                a[r].z += __shfl_xor_sync(0xffffffffu, a[r].z, off);
                a[r].w += __shfl_xor_sync(0xffffffffu, a[r].w, off);
                b[r].x += __shfl_xor_sync(0xffffffffu, b[r].x, off);
                b[r].y += __shfl_xor_sync(0xffffffffu, b[r].y, off);
                b[r].z += __shfl_xor_sync(0xffffffffu, b[r].z, off);
                b[r].w += __shfl_xor_sync(0xffffffffu, b[r].w, off);
            }
            if (lane < 2) {
                int q0 = lane * 8;
                int w = wbase + r;
                g_BvT[(q0 + 0) * WW + w] = a[r].x;
                g_BvT[(q0 + 1) * WW + w] = a[r].y;
                g_BvT[(q0 + 2) * WW + w] = a[r].z;
                g_BvT[(q0 + 3) * WW + w] = a[r].w;
                g_BvT[(q0 + 4) * WW + w] = b[r].x;
                g_BvT[(q0 + 5) * WW + w] = b[r].y;
                g_BvT[(q0 + 6) * WW + w] = b[r].z;
                g_BvT[(q0 + 7) * WW + w] = b[r].w;
            }
        }
    }
}

// ---------------------------------------------------------------------------
// Kernel B (R5-proven stage1): T[bc,p,w] = sum_q K[bc,p,q] * Bv[w,q]
//   grid (2, BC), 256 threads; thread owns one w, all 16 p. Coalesced stores.
// ---------------------------------------------------------------------------
__global__ __launch_bounds__(256) void stage1(const float* __restrict__ K) {
    int bc = blockIdx.y;
    int w = blockIdx.x * 256 + threadIdx.x;

    __shared__ float sK[PP * QQ];
    sK[threadIdx.x] = K[(size_t)bc * (PP * QQ) + threadIdx.x];

    float rv[QQ];
    #pragma unroll
    for (int q = 0; q < QQ; ++q) rv[q] = g_BvT[q * WW + w];
    __syncthreads();

    float* tb = g_T + (size_t)bc * PP * WW + w;
    #pragma unroll
    for (int p = 0; p < PP; ++p) {
        float s = 0.f;
        #pragma unroll
        for (int q = 0; q < QQ; ++q) s = fmaf(sK[p * QQ + q], rv[q], s);
        tb[p * WW] = s;
    }
}

// ---------------------------------------------------------------------------
// Kernel C (R13-proven fused, unchanged): out[bc,h,w] = sum_p Bu[h,p]*T[bc,p,w]
//   grid (H/ROWS=8, BC), 128 threads; thread t owns w = 4t..4t+3.
//   Accumulator pairs packed over h; Bu = natural pair via broadcast LDS.128;
//   T dup'd once into register pairs.
// ---------------------------------------------------------------------------
__global__ __launch_bounds__(128) void fused_stage(float* __restrict__ out) {
    int bc = blockIdx.y;
    int h0 = blockIdx.x * ROWS;
    int t = threadIdx.x;

    __shared__ float sBu[PP * ROWS];   // [p][hh], 4 KB

    // Stage Bu tile (coalesced float4 copy)
    {
        const float4* src = reinterpret_cast<const float4*>(g_But);
        float4* dst = reinterpret_cast<float4*>(sBu);
        #pragma unroll
        for (int i = t; i < PP * ROWS / 4; i += 128) {
            int p = i >> 4, c = i & 15;
            dst[i] = src[(p * HH + h0) / 4 + c];
        }
    }

    // Load T[p][4t..4t+3] and duplicate into register pairs
    unsigned long long Td[PP][4];
    {
        const float4* t4 = reinterpret_cast<const float4*>(g_T + (size_t)bc * PP * WW);
        #pragma unroll
        for (int p = 0; p < PP; ++p) {
            float4 tl = t4[p * (WW / 4) + t];
            Td[p][0] = pk(tl.x, tl.x);
            Td[p][1] = pk(tl.y, tl.y);
            Td[p][2] = pk(tl.z, tl.z);
            Td[p][3] = pk(tl.w, tl.w);
        }
    }
    __syncthreads();

    float* obase = out + (size_t)bc * HH * WW + (size_t)h0 * WW + 4 * t;

    #pragma unroll 2
    for (int g = 0; g < ROWS; g += 4) {
        unsigned long long acc[4][2];
        #pragma unroll
        for (int w = 0; w < 4; ++w) { acc[w][0] = 0ull; acc[w][1] = 0ull; }

        #pragma unroll
        for (int p = 0; p < PP; ++p) {
            // Broadcast LDS.128: Bu for h = h0+g..h0+g+3, as 2 natural pairs
            ulonglong2 v = *reinterpret_cast<const ulonglong2*>(&sBu[p * ROWS + g]);
            fma2(acc[0][0], v.x, Td[p][0]);
            fma2(acc[1][0], v.x, Td[p][1]);
            fma2(acc[2][0], v.x, Td[p][2]);
            fma2(acc[3][0], v.x, Td[p][3]);
            fma2(acc[0][1], v.y, Td[p][0]);
            fma2(acc[1][1], v.y, Td[p][1]);
            fma2(acc[2][1], v.y, Td[p][2]);
            fma2(acc[3][1], v.y, Td[p][3]);
        }

        float r0[4], r1[4], r2[4], r3[4];
        #pragma unroll
        for (int w = 0; w < 4; ++w) {
            unpk(acc[w][0], r0[w], r1[w]);   // rows g, g+1
            unpk(acc[w][1], r2[w], r3[w]);   // rows g+2, g+3
        }
        *reinterpret_cast<float4*>(obase + (size_t)(g + 0) * WW) = make_float4(r0[0], r0[1], r0[2], r0[3]);
        *reinterpret_cast<float4*>(obase + (size_t)(g + 1) * WW) = make_float4(r1[0], r1[1], r1[2], r1[3]);
        *reinterpret_cast<float4*>(obase + (size_t)(g + 2) * WW) = make_float4(r2[0], r2[1], r2[2], r2[3]);
        *reinterpret_cast<float4*>(obase + (size_t)(g + 3) * WW) = make_float4(r3[0], r3[1], r3[2], r3[3]);
    }
}

// ---------------------------------------------------------------------------
extern "C" void kernel_launch(void* const* d_in, const int* in_sizes, int n_in,
                              void* d_out, int out_size) {
    const float* K     = (const float*)d_in[0];
    const float* basis = (const float*)d_in[1];
    float* out = (float*)d_out;
    (void)in_sizes; (void)n_in; (void)out_size;

    extract_factors<<<32, 256>>>(basis);

    dim3 g1(2, BC);
    stage1<<<g1, 256>>>(K);

    dim3 g2(HH / ROWS, BC);
    fused_stage<<<g2, 128>>>(out);
}